// round 11
// baseline (speedup 1.0000x reference)
#include <cuda_runtime.h>
#include <cstdint>
#include <cstddef>

#define NB    32
#define TT    2048
#define MMI   64
#define PPO   64
#define NSTA  512
#define NROWS (NB * TT)
#define KB    16              // trace block (time steps)
#define CHUNK 256             // time chunk per k_x CTA
#define NCH   (TT / CHUNK)    // 8
#define ZK    128             // z-IIR block

__device__ float g_Bu[NROWS * NSTA];
__device__ float g_x [NROWS * NSTA];
__device__ float g_d [NB * TT];
__device__ float g_z [NB * (TT + 1)];

// ---------------------------------------------------------------------------
__global__ void k_zero_d() {
    int i = blockIdx.x * blockDim.x + threadIdx.x;
    reinterpret_cast<float4*>(g_d)[i] = make_float4(0.f, 0.f, 0.f, 0.f);
}

// ---------------------------------------------------------------------------
// K1: Bu = u @ B^T, fused with anti-diagonal partial sums for d.
// (unchanged — measured at the fp32 FFMA roofline)
// ---------------------------------------------------------------------------
__global__ void __launch_bounds__(256) k_bu(const float* __restrict__ u,
                                            const float* __restrict__ Bm) {
    __shared__ float us[128][33];
    __shared__ float bs[64][33];
    __shared__ float dsh[192];

    const int r0  = blockIdx.x * 128;
    const int n0  = blockIdx.y * 64;
    const int tid = threadIdx.x;
    const int tx  = tid & 15;
    const int ty  = tid >> 4;
    const int lr  = tid >> 3;
    const int lk  = (tid & 7) * 4;

    if (tid < 192) dsh[tid] = 0.f;

    float acc[8][4];
#pragma unroll
    for (int i = 0; i < 8; i++)
#pragma unroll
        for (int j = 0; j < 4; j++) acc[i][j] = 0.0f;

#pragma unroll
    for (int c = 0; c < 2; c++) {
#pragma unroll
        for (int pass = 0; pass < 4; ++pass) {
            int row = lr + pass * 32;
            float4 v = *reinterpret_cast<const float4*>(
                u + (size_t)(r0 + row) * MMI + c * 32 + lk);
            us[row][lk + 0] = v.x; us[row][lk + 1] = v.y;
            us[row][lk + 2] = v.z; us[row][lk + 3] = v.w;
        }
#pragma unroll
        for (int pass = 0; pass < 2; ++pass) {
            int n = lr + pass * 32;
            float4 v = *reinterpret_cast<const float4*>(
                Bm + (size_t)(n0 + n) * MMI + c * 32 + lk);
            bs[n][lk + 0] = v.x; bs[n][lk + 1] = v.y;
            bs[n][lk + 2] = v.z; bs[n][lk + 3] = v.w;
        }
        __syncthreads();
#pragma unroll
        for (int k = 0; k < 32; k++) {
            float av[8], bv[4];
#pragma unroll
            for (int i = 0; i < 8; i++) av[i] = us[ty * 8 + i][k];
#pragma unroll
            for (int j = 0; j < 4; j++) bv[j] = bs[tx * 4 + j][k];
#pragma unroll
            for (int i = 0; i < 8; i++)
#pragma unroll
                for (int j = 0; j < 4; j++)
                    acc[i][j] = fmaf(av[i], bv[j], acc[i][j]);
        }
        __syncthreads();
    }

#pragma unroll
    for (int i = 0; i < 8; i++) {
        float4 v = make_float4(acc[i][0], acc[i][1], acc[i][2], acc[i][3]);
        *reinterpret_cast<float4*>(
            g_Bu + (size_t)(r0 + ty * 8 + i) * NSTA + n0 + tx * 4) = v;
    }

    float dl[11];
#pragma unroll
    for (int q = 0; q < 11; q++) dl[q] = 0.f;
#pragma unroll
    for (int i = 0; i < 8; i++)
#pragma unroll
        for (int j = 0; j < 4; j++) dl[i - j + 3] += acc[i][j];
    const int obase = ty * 8 - tx * 4 + 60;
#pragma unroll
    for (int q = 0; q < 11; q++) atomicAdd(&dsh[obase + q], dl[q]);
    __syncthreads();
    if (tid < 192) {
        int bb  = r0 >> 11;
        int idx = (r0 & 2047) + 448 - n0 + tid;
        if (idx < TT) atomicAdd(&g_d[bb * TT + idx], dsh[tid]);
    }
}

// ---------------------------------------------------------------------------
// K2a: scalar 512-tap IIR per batch (unchanged)
// ---------------------------------------------------------------------------
__global__ void __launch_bounds__(512) k_ziir(const float* __restrict__ a) {
    __shared__ float zb[2561];
    __shared__ float as[512];
    __shared__ float gs[ZK];
    __shared__ float bsol[ZK];

    const int b   = blockIdx.x;
    const int tid = threadIdx.x;

    as[tid] = a[tid];
    for (int i = tid; i < 2561; i += 512) zb[i] = 0.f;
    __syncthreads();

    if (tid < 32) {
        const int l = tid;
        for (int c = 0; c < ZK; c += 32) {
            const int q = c + l;
            float H = 0.f;
            for (int j = q - c + 1; j <= q; j++)
                H += as[j - 1] * gs[q - j];
            float inner = 0.f;
            for (int m = 0; m < 32; m++) {
                float v = -(H + inner);
                if (c == 0 && m == 0) v = 1.f;
                float gval = __shfl_sync(0xffffffffu, v, m);
                if (l == m) gs[q] = gval;
                else if (l > m) inner += as[l - m - 1] * gval;
            }
            __syncwarp();
        }
    }
    __syncthreads();

    const float* dp = g_d + (size_t)b * TT;
    const int k4 = (tid >> 2) + 1;
    const int qq = tid & 3;

    for (int blk = 0; blk < TT / ZK; blk++) {
        const int T0 = blk * ZK;
        const int t  = T0 + k4;
        float H = 0.f;
        for (int j = k4 + qq; j <= 512; j += 4)
            H += as[j - 1] * zb[512 + t - j];
        H += __shfl_xor_sync(0xffffffffu, H, 1);
        H += __shfl_xor_sync(0xffffffffu, H, 2);
        if (qq == 0) bsol[k4 - 1] = dp[t - 1] - H;
        __syncthreads();
        float zv = 0.f;
        for (int m = 1 + qq; m <= k4; m += 4)
            zv += gs[k4 - m] * bsol[m - 1];
        zv += __shfl_xor_sync(0xffffffffu, zv, 1);
        zv += __shfl_xor_sync(0xffffffffu, zv, 2);
        if (qq == 0) zb[512 + t] = zv;
        __syncthreads();
    }

    for (int t = tid; t <= TT; t += 512)
        g_z[(size_t)b * (TT + 1) + t] = zb[512 + t];
}

// ---------------------------------------------------------------------------
// K2b: parallel state materialization.
// RESTRUCTURED: KB=16 (smem 70KB -> 2 CTAs/SM), CHUNK=256 (grid 256 CTAs).
// Warm-up = min(c*CHUNK, 512): exact, because a chunk warmed from t=0 needs
// no longer history, and 512 steps cover all diagonals otherwise.
// ---------------------------------------------------------------------------
struct XSmem {
    float butile[2][KB * NSTA];  // 2 x 32KB
    float xs[2][NSTA];
    float fs[NSTA];
    float zs[2][KB];
};

__device__ __forceinline__ unsigned su32(const void* p) {
    return (unsigned)__cvta_generic_to_shared(p);
}
__device__ __forceinline__ void cp16(void* smem_dst, const void* gsrc) {
    asm volatile("cp.async.cg.shared.global [%0], [%1], 16;"
                 :: "r"(su32(smem_dst)), "l"(gsrc));
}
__device__ __forceinline__ void cp_commit() { asm volatile("cp.async.commit_group;"); }
__device__ __forceinline__ void cp_wait0()  { asm volatile("cp.async.wait_group 0;"); }

__global__ void __launch_bounds__(512, 2) k_x(const float* __restrict__ a) {
    extern __shared__ char raw[];
    XSmem* s = reinterpret_cast<XSmem*>(raw);
    const int b = blockIdx.x >> 3;   // batch
    const int c = blockIdx.x & 7;    // chunk
    const int i = threadIdx.x;

    s->fs[i] = -a[511 - i];
    s->xs[0][i] = 0.f;

    const int warm    = (c * CHUNK < 512) ? c * CHUNK : 512;
    const int base_t  = c * CHUNK - warm;
    const int nblk    = (warm + CHUNK) / KB;
    const int wstore0 = warm / KB;

    const float* bu_g = g_Bu + ((size_t)b * TT + base_t) * NSTA;
    const float* z_g  = g_z + (size_t)b * (TT + 1) + base_t;
    float*       xo   = g_x + (size_t)b * TT * NSTA;

    {   // preload tile 0 (KB*NSTA = 8192 floats = 2048 float4)
        float* dst = s->butile[0];
#pragma unroll
        for (int r = 0; r < 4; r++) { int q = i + r * 512; cp16(dst + q * 4, bu_g + q * 4); }
        cp_commit(); cp_wait0();
    }
    if (i < KB) s->zs[0][i] = z_g[i];
    __syncthreads();

    for (int w = 0; w < nblk; w++) {
        const int cur = w & 1;
        const float* bu  = s->butile[cur];
        const float* xsc = s->xs[cur];
        const float* zsc = s->zs[cur];

        if (w + 1 < nblk) {
            const float* src = bu_g + (size_t)(w + 1) * KB * NSTA;
            float* dst = s->butile[cur ^ 1];
#pragma unroll
            for (int r = 0; r < 4; r++) { int q = i + r * 512; cp16(dst + q * 4, src + q * 4); }
            cp_commit();
            if (i < KB) s->zs[cur ^ 1][i] = z_g[(size_t)(w + 1) * KB + i];
        }

        const bool st = (w >= wstore0);
        const int  tb = base_t + w * KB;        // t = tb+1 .. tb+KB
        float v  = (i >= KB) ? xsc[i - KB]          : 0.f;  // origin i-KB
        float v2 = (i <  KB) ? xsc[NSTA - KB + i]   : 0.f;  // origin 496+i

#pragma unroll
        for (int k = 1; k <= KB; k++) {
            const float zk = zsc[k - 1];        // z_{t-1}
            int p = i - KB + k;
            if (p == 0) {
                v = s->fs[0] * zk + bu[(k - 1) * NSTA];
                if (st) xo[(size_t)(tb + k - 1) * NSTA] = v;
            } else if (p > 0) {
                v += s->fs[p] * zk + bu[(k - 1) * NSTA + p];
                if (st) xo[(size_t)(tb + k - 1) * NSTA + p] = v;
            }
            if (i < KB) {
                int p2 = NSTA - KB + i + k;
                if (p2 < NSTA) {
                    v2 += s->fs[p2] * zk + bu[(k - 1) * NSTA + p2];
                    if (st) xo[(size_t)(tb + k - 1) * NSTA + p2] = v2;
                }
            }
        }
        s->xs[cur ^ 1][i] = v;
        cp_wait0();
        __syncthreads();
    }
}

// ---------------------------------------------------------------------------
// K3: y = x @ C^T + u @ D^T   (unchanged — at the fp32 FFMA roofline)
// ---------------------------------------------------------------------------
__global__ void __launch_bounds__(256) k_out(const float* __restrict__ u,
                                             const float* __restrict__ Cm,
                                             const float* __restrict__ Dm,
                                             float* __restrict__ y) {
    __shared__ float xs[128][33];
    __shared__ float cs[64][33];

    const int r0  = blockIdx.x * 128;
    const int tid = threadIdx.x;
    const int tx  = tid & 15;
    const int ty  = tid >> 4;
    const int lr  = tid >> 3;
    const int lk  = (tid & 7) * 4;

    float acc[8][4];
#pragma unroll
    for (int i = 0; i < 8; i++)
#pragma unroll
        for (int j = 0; j < 4; j++) acc[i][j] = 0.0f;

    for (int c = 0; c < 16; c++) {
#pragma unroll
        for (int pass = 0; pass < 4; ++pass) {
            int row = lr + pass * 32;
            float4 v = *reinterpret_cast<const float4*>(
                g_x + (size_t)(r0 + row) * NSTA + c * 32 + lk);
            xs[row][lk + 0] = v.x; xs[row][lk + 1] = v.y;
            xs[row][lk + 2] = v.z; xs[row][lk + 3] = v.w;
        }
#pragma unroll
        for (int pass = 0; pass < 2; ++pass) {
            int p = lr + pass * 32;
            float4 v = *reinterpret_cast<const float4*>(
                Cm + (size_t)p * NSTA + c * 32 + lk);
            cs[p][lk + 0] = v.x; cs[p][lk + 1] = v.y;
            cs[p][lk + 2] = v.z; cs[p][lk + 3] = v.w;
        }
        __syncthreads();
#pragma unroll
        for (int k = 0; k < 32; k++) {
            float av[8], bv[4];
#pragma unroll
            for (int i = 0; i < 8; i++) av[i] = xs[ty * 8 + i][k];
#pragma unroll
            for (int j = 0; j < 4; j++) bv[j] = cs[tx * 4 + j][k];
#pragma unroll
            for (int i = 0; i < 8; i++)
#pragma unroll
                for (int j = 0; j < 4; j++)
                    acc[i][j] = fmaf(av[i], bv[j], acc[i][j]);
        }
        __syncthreads();
    }

#pragma unroll
    for (int c = 0; c < 2; c++) {
#pragma unroll
        for (int pass = 0; pass < 4; ++pass) {
            int row = lr + pass * 32;
            float4 v = *reinterpret_cast<const float4*>(
                u + (size_t)(r0 + row) * MMI + c * 32 + lk);
            xs[row][lk + 0] = v.x; xs[row][lk + 1] = v.y;
            xs[row][lk + 2] = v.z; xs[row][lk + 3] = v.w;
        }
#pragma unroll
        for (int pass = 0; pass < 2; ++pass) {
            int p = lr + pass * 32;
            float4 v = *reinterpret_cast<const float4*>(
                Dm + (size_t)p * MMI + c * 32 + lk);
            cs[p][lk + 0] = v.x; cs[p][lk + 1] = v.y;
            cs[p][lk + 2] = v.z; cs[p][lk + 3] = v.w;
        }
        __syncthreads();
#pragma unroll
        for (int k = 0; k < 32; k++) {
            float av[8], bv[4];
#pragma unroll
            for (int i = 0; i < 8; i++) av[i] = xs[ty * 8 + i][k];
#pragma unroll
            for (int j = 0; j < 4; j++) bv[j] = cs[tx * 4 + j][k];
#pragma unroll
            for (int i = 0; i < 8; i++)
#pragma unroll
                for (int j = 0; j < 4; j++)
                    acc[i][j] = fmaf(av[i], bv[j], acc[i][j]);
        }
        __syncthreads();
    }

#pragma unroll
    for (int i = 0; i < 8; i++) {
        float4 v = make_float4(acc[i][0], acc[i][1], acc[i][2], acc[i][3]);
        *reinterpret_cast<float4*>(
            y + (size_t)(r0 + ty * 8 + i) * PPO + tx * 4) = v;
    }
}

// ---------------------------------------------------------------------------
extern "C" void kernel_launch(void* const* d_in, const int* in_sizes, int n_in,
                              void* d_out, int out_size) {
    const float* u  = (const float*)d_in[0];
    const float* a  = (const float*)d_in[1];
    const float* Bm = (const float*)d_in[2];
    const float* Cm = (const float*)d_in[3];
    const float* Dm = (const float*)d_in[4];
    float* y = (float*)d_out;
    (void)in_sizes; (void)n_in; (void)out_size;

    k_zero_d<<<(NB * TT / 4) / 256, 256>>>();
    k_bu<<<dim3(NROWS / 128, NSTA / 64), 256>>>(u, Bm);
    k_ziir<<<NB, 512>>>(a);

    cudaFuncSetAttribute(k_x, cudaFuncAttributeMaxDynamicSharedMemorySize,
                         (int)sizeof(XSmem));
    k_x<<<NB * NCH, 512, sizeof(XSmem)>>>(a);

    k_out<<<NROWS / 128, 256>>>(u, Cm, Dm, y);
}